// round 6
// baseline (speedup 1.0000x reference)
#include <cuda_runtime.h>
#include <stdint.h>

// Problem constants (fixed shapes per reference)
#define VOCAB   20000
#define TOPK    8
#define GLOVE   300
#define ROW_F   (TOPK * 2 * GLOVE)   // 4800 floats per vocab row
#define OUTC    100
#define B       32
#define L       128
#define NLAB    8
#define NPOS    (B * L)              // 4096
#define NLABTOT (NPOS * NLAB)        // 32768

// Device scratch (no allocations allowed)
__device__ unsigned int g_flags[VOCAB];
__device__ float g_lsum[VOCAB * GLOVE];   // 24 MB: per-vocab summed+prescaled 300-vec
__device__ float g_A[NPOS * GLOVE];       // 4.9 MB: per-position averaged 300-vec

#define FMA2(acc, a, w) \
    asm("fma.rn.f32x2 %0, %1, %2, %0;" : "+l"(acc) : "l"(a), "l"(w))
#define DUP2(d, s) \
    asm("mov.b64 %0, {%1, %1};" : "=l"(d) : "f"(s))
#define UNPK2(lo, hi, v) \
    asm("mov.b64 {%0, %1}, %2;" : "=f"(lo), "=f"(hi) : "l"(v))

// ---------------------------------------------------------------------------
// Kernel 1: clear usage flags
// ---------------------------------------------------------------------------
__global__ void k_clear_flags() {
    int i = blockIdx.x * blockDim.x + threadIdx.x;
    if (i < VOCAB) g_flags[i] = 0u;
}

// ---------------------------------------------------------------------------
// Kernel 2: mark used vocab entries
// ---------------------------------------------------------------------------
__global__ void k_mark_flags(const int* __restrict__ labels) {
    int i = blockIdx.x * blockDim.x + threadIdx.x;
    if (i < NLABTOT) g_flags[labels[i]] = 1u;
}

// ---------------------------------------------------------------------------
// Kernel 3: per-vocab row reduction (DRAM-streaming bound, ~310 MB total).
// One block per vocab row; only flagged rows do work. At the DRAM floor.
// ---------------------------------------------------------------------------
__global__ __launch_bounds__(256) void k_rowsum(const float* __restrict__ table) {
    const int v = blockIdx.x;
    if (!g_flags[v]) return;
    const float* __restrict__ row = table + (size_t)v * ROW_F;
    const int t = threadIdx.x;
    const float scale = 1.0f / 128.0f;

    {
        float s = 0.0f;
        #pragma unroll
        for (int r = 0; r < 16; ++r) s += row[r * GLOVE + t];
        g_lsum[v * GLOVE + t] = s * scale;
    }
    if (t < GLOVE - 256) {
        const int d = t + 256;
        float s = 0.0f;
        #pragma unroll
        for (int r = 0; r < 16; ++r) s += row[r * GLOVE + d];
        g_lsum[v * GLOVE + d] = s * scale;
    }
}

// ---------------------------------------------------------------------------
// Kernel 4: averaging gather. One float4 per thread: 4096*75 = 307200 threads.
// ---------------------------------------------------------------------------
#define GATHER_THREADS 256
#define GATHER_TOTAL   (NPOS * (GLOVE / 4))   // 307200

__global__ __launch_bounds__(GATHER_THREADS) void k_gather(const int* __restrict__ labels) {
    const int i = blockIdx.x * GATHER_THREADS + threadIdx.x;
    if (i >= GATHER_TOTAL) return;
    const int p  = i / (GLOVE / 4);
    const int k  = (i % (GLOVE / 4)) * 4;

    const int* __restrict__ lab = labels + p * NLAB;
    int l[NLAB];
    #pragma unroll
    for (int j = 0; j < NLAB; ++j) l[j] = lab[j];

    float4 s = make_float4(0.f, 0.f, 0.f, 0.f);
    #pragma unroll
    for (int j = 0; j < NLAB; ++j) {
        const float4 v = *reinterpret_cast<const float4*>(&g_lsum[l[j] * GLOVE + k]);
        s.x += v.x; s.y += v.y; s.z += v.z; s.w += v.w;
    }
    *reinterpret_cast<float4*>(&g_A[p * GLOVE + k]) = s;
}

// ---------------------------------------------------------------------------
// Kernel 5 (v5): GEMM  out[4096,100] = A[4096,300] * W^T + bias.
// Grid 512 = 256 pos-tiles x 2 out-tiles. Block: 16 pos x 50 outs, 200 thr.
// Thread tile: 2 pos x 2 outs, accs packed f32x2 over the POS pair so the
// A operand is a single packed LDS.64 with no duplication.
// smem: A transposed [300][18], W transposed [300][52]  (84 KB -> 2 blk/SM).
// Inner loop per k: 2x LDS.64 + 2 DUP + 2 FFMA2 = 6 instr / 4 MACs.
// ---------------------------------------------------------------------------
#define POS_T    16
#define OUT_T    50
#define GT5      200
#define APITCH5  18
#define WPITCH5  52

__global__ __launch_bounds__(GT5) void k_gemm5(
    const float* __restrict__ w,      // [100, 300]
    const float* __restrict__ bias,   // [100]
    float* __restrict__ out)          // [4096, 100]
{
    __shared__ float A_t[GLOVE][APITCH5];   // [k][pos]
    __shared__ float W_t[GLOVE][WPITCH5];   // [k][out]

    const int tid   = threadIdx.x;
    const int pbase = (blockIdx.x >> 1) * POS_T;
    const int obase = (blockIdx.x & 1) * OUT_T;
    const int pgrp  = tid / 25;    // 0..7  -> pos pair pgrp*2, pgrp*2+1
    const int ogrp  = tid % 25;    // 0..24 -> out pair ogrp*2, ogrp*2+1

    // Stage W slice transposed: coalesced global read over k.
    for (int o = 0; o < OUT_T; ++o)
        for (int kk = tid; kk < GLOVE; kk += GT5)
            W_t[kk][o] = w[(obase + o) * GLOVE + kk];

    // Stage A slice transposed: coalesced global read over k.
    for (int pp = 0; pp < POS_T; ++pp)
        for (int kk = tid; kk < GLOVE; kk += GT5)
            A_t[kk][pp] = g_A[(pbase + pp) * GLOVE + kk];

    __syncthreads();

    unsigned long long acc0 = 0ull, acc1 = 0ull;   // (p0,p1) for out o0 / o1
    const int pa = pgrp * 2;
    const int oa = ogrp * 2;

    #pragma unroll 4
    for (int k = 0; k < GLOVE; ++k) {
        unsigned long long a01 =
            *reinterpret_cast<const unsigned long long*>(&A_t[k][pa]);
        const float2 wv = *reinterpret_cast<const float2*>(&W_t[k][oa]);
        unsigned long long w0d, w1d;
        DUP2(w0d, wv.x);
        DUP2(w1d, wv.y);
        FMA2(acc0, a01, w0d);
        FMA2(acc1, a01, w1d);
    }

    // Epilogue
    float p0o0, p1o0, p0o1, p1o1;
    UNPK2(p0o0, p1o0, acc0);
    UNPK2(p0o1, p1o1, acc1);
    const float b0 = bias[obase + oa];
    const float b1 = bias[obase + oa + 1];
    const int p0 = pbase + pa, p1 = p0 + 1;
    const int o0 = obase + oa, o1 = o0 + 1;
    out[p0 * OUTC + o0] = p0o0 + b0;
    out[p0 * OUTC + o1] = p0o1 + b1;
    out[p1 * OUTC + o0] = p1o0 + b0;
    out[p1 * OUTC + o1] = p1o1 + b1;
}

// ---------------------------------------------------------------------------
extern "C" void kernel_launch(void* const* d_in, const int* in_sizes, int n_in,
                              void* d_out, int out_size) {
    const int*   labels = (const int*)  d_in[0];   // [32, 128, 8] int32
    const float* table  = (const float*)d_in[1];   // [20000, 8, 600] f32
    const float* conv_w = (const float*)d_in[2];   // [100, 300]
    const float* conv_b = (const float*)d_in[3];   // [100]
    float*       out    = (float*)d_out;           // [32, 128, 100]

    (void)in_sizes; (void)n_in; (void)out_size;

    k_clear_flags<<<(VOCAB + 255) / 256, 256>>>();
    k_mark_flags<<<(NLABTOT + 255) / 256, 256>>>(labels);
    k_rowsum<<<VOCAB, 256>>>(table);
    k_gather<<<(GATHER_TOTAL + GATHER_THREADS - 1) / GATHER_THREADS, GATHER_THREADS>>>(labels);
    k_gemm5<<<(NPOS / POS_T) * 2, GT5>>>(conv_w, conv_b, out);
}